// round 16
// baseline (speedup 1.0000x reference)
#include <cuda_runtime.h>
#include <cuda_fp16.h>
#include <cstdint>

// ResLSTM on GB300, round 16: gate-split warp pairs (R15) with the stash
// aliasing bug fixed: layer-0 head partials now live in a DEDICATED smem
// region (OFF_PH), not the pair-exchange buffer (which layer-1's recurrence
// overwrites every timestep -- the R15 rel_err=0.89 bug).
// CTA = 128 batches, 512 threads (16 warps = 8 pairs). Pair owns 16 batch
// rows; warp A computes gate cols 0..63 (i,f), warp B cols 64..127 (g,o)
// -> acc[8][4] = 32 regs (kills the 255-reg spills of R11/R14).
// Cell math via raw-f32 gate exchange + named barrier (bar.sync pair+1, 64).
// Swizzle always applied to the full unswizzled offset (R12 lesson).

#define MB       128
#define NT       512
#define TT       5
#define NF       62
#define B_TOTAL  131072
#define TILE_B   16384     // [128 rows][64 half] = 128B rows

#define OFF_X     0                       // 5 tiles: x -> o0 -> x1 -> o1
#define OFF_H     (5 * TILE_B)            // 81920
#define OFF_WI0   (OFF_H + TILE_B)        // 98304
#define OFF_WH0   (OFF_WI0 + TILE_B)
#define OFF_WI1   (OFF_WH0 + TILE_B)
#define OFF_WH1   (OFF_WI1 + TILE_B)
#define OFF_EXCH  (OFF_WH1 + TILE_B)      // 163840, 8 pairs x 4KB = 32KB
#define OFF_PH    (OFF_EXCH + 32768)      // 128 x 3 f32 head-partial stash
#define OFF_BIAS0 (OFF_PH + 1536)         // 128 f32
#define OFF_BIAS1 (OFF_BIAS0 + 512)
#define OFF_G0    (OFF_BIAS1 + 512)       // 160 f32
#define OFF_BE0   (OFF_G0 + 640)
#define OFF_G1    (OFF_BE0 + 640)
#define OFF_BE1   (OFF_G1 + 640)
#define OFF_DW    (OFF_BE1 + 640)         // 480 f32
#define OFF_DB    (OFF_DW + 1920)
#define SMEM_TOTAL (OFF_DB + 16)          // ~204 KB

#define SWZ(x) ((x) ^ (((x) >> 3) & 0x70))

__device__ __forceinline__ uint32_t smem_u32(const void* p) {
    uint32_t a;
    asm("{ .reg .u64 t; cvta.to.shared.u64 t, %1; cvt.u32.u64 %0, t; }"
        : "=r"(a) : "l"(p));
    return a;
}
__device__ __forceinline__ float tanh_f(float x) {
    float y; asm("tanh.approx.f32 %0, %1;" : "=f"(y) : "f"(x)); return y;
}
__device__ __forceinline__ float sigm(float x) {
    return fmaf(0.5f, tanh_f(0.5f * x), 0.5f);
}
__device__ __forceinline__ float lrelu(float x) {
    return x > 0.0f ? x : 0.01f * x;
}
__device__ __forceinline__ void ldm4(uint32_t a, uint32_t& r0, uint32_t& r1,
                                     uint32_t& r2, uint32_t& r3) {
    asm volatile("ldmatrix.sync.aligned.m8n8.x4.shared.b16 {%0,%1,%2,%3}, [%4];"
                 : "=r"(r0), "=r"(r1), "=r"(r2), "=r"(r3) : "r"(a));
}
__device__ __forceinline__ void mma16816(float* c, uint32_t a0, uint32_t a1,
                                         uint32_t a2, uint32_t a3,
                                         uint32_t b0, uint32_t b1) {
    asm volatile(
        "mma.sync.aligned.m16n8k16.row.col.f32.f16.f16.f32 "
        "{%0,%1,%2,%3}, {%4,%5,%6,%7}, {%8,%9}, {%0,%1,%2,%3};"
        : "+f"(c[0]), "+f"(c[1]), "+f"(c[2]), "+f"(c[3])
        : "r"(a0), "r"(a1), "r"(a2), "r"(a3), "r"(b0), "r"(b1));
}
#define BARP(id) asm volatile("bar.sync %0, 64;" :: "r"(id) : "memory")

// One GEMM phase, 8 n-tiles (this warp's 64 gate columns).
// A/B tiles: 128B rows SW128. Swizzle on the FULL unswizzled offset;
// np stride 2048 sits above the swizzle input bits.
template <int KC>
__device__ __forceinline__ void gemm_phase(
    uint32_t Atile, uint32_t Btile, uint32_t aun, uint32_t bun,
    float (&acc)[8][4])
{
#pragma unroll
    for (int kc = 0; kc < KC; kc++) {
        uint32_t a0, a1, a2, a3;
        ldm4(Atile + SWZ(aun + kc * 32), a0, a1, a2, a3);
        uint32_t bsw = SWZ(bun + kc * 32);
#pragma unroll
        for (int np = 0; np < 4; np++) {
            uint32_t b0, b1, b2, b3;
            ldm4(Btile + bsw + np * 2048, b0, b1, b2, b3);
            mma16816(acc[2 * np],     a0, a1, a2, a3, b0, b1);
            mma16816(acc[2 * np + 1], a0, a1, a2, a3, b2, b3);
        }
    }
}

__global__ __launch_bounds__(NT, 1) void reslstm_mma(
    const float* __restrict__ data,
    const float* __restrict__ w_ih0, const float* __restrict__ w_hh0,
    const float* __restrict__ b_ih0, const float* __restrict__ b_hh0,
    const float* __restrict__ g0,    const float* __restrict__ be0,
    const float* __restrict__ w_ih1, const float* __restrict__ w_hh1,
    const float* __restrict__ b_ih1, const float* __restrict__ b_hh1,
    const float* __restrict__ g1,    const float* __restrict__ be1,
    const float* __restrict__ dw,    const float* __restrict__ db,
    float* __restrict__ out)
{
    extern __shared__ char smem[];
    const uint32_t sb = smem_u32(smem);
    const int tid = threadIdx.x;
    const int l   = tid & 31;
    const int w   = tid >> 5;           // 0..15
    const int pair   = w >> 1;          // 0..7
    const int inPair = w & 1;           // 0 = (i,f), 1 = (g,o)
    const int warpRow = pair * 16;
    const long long gbase = (long long)blockIdx.x * MB;

    // ---- staging ----
    for (int i = tid; i < TILE_B / 16; i += NT)
        ((uint4*)(smem + OFF_H))[i] = make_uint4(0, 0, 0, 0);

    for (int i = tid; i < MB * NF * TT; i += NT) {
        int m = i / (NF * TT);
        int rem = i - m * (NF * TT);
        int n = rem / TT;
        int t = rem - n * TT;
        float v = data[((gbase + m) * NF + n) * TT + t];
        *(__half*)(smem + OFF_X + t * TILE_B + SWZ((uint32_t)(m * 128 + n * 2)))
            = __float2half(v);
    }
    for (int i = tid; i < MB * TT; i += NT) {   // pad n = 62,63
        int m = i / TT, t = i - m * TT;
        *(uint32_t*)(smem + OFF_X + t * TILE_B + SWZ((uint32_t)(m * 128 + 124))) = 0u;
    }
    for (int i = tid; i < 128 * 64; i += NT) {  // weights [n=col][k], fp16
        int r = i >> 6, k = i & 63;
        uint32_t so = SWZ((uint32_t)(r * 128 + k * 2));
        *(__half*)(smem + OFF_WI0 + so) = __float2half(k < NF ? w_ih0[r * NF + k] : 0.f);
        *(__half*)(smem + OFF_WH0 + so) = __float2half(k < 32 ? w_hh0[r * 32 + k] : 0.f);
        *(__half*)(smem + OFF_WI1 + so) = __float2half(k < 32 ? w_ih1[r * 32 + k] : 0.f);
        *(__half*)(smem + OFF_WH1 + so) = __float2half(k < 32 ? w_hh1[r * 32 + k] : 0.f);
    }
    if (tid < 128) {
        ((float*)(smem + OFF_BIAS0))[tid] = b_ih0[tid] + b_hh0[tid];
        ((float*)(smem + OFF_BIAS1))[tid] = b_ih1[tid] + b_hh1[tid];
    }
    for (int i = tid; i < 160; i += NT) {
        ((float*)(smem + OFF_G0))[i]  = g0[i];
        ((float*)(smem + OFF_BE0))[i] = be0[i];
        ((float*)(smem + OFF_G1))[i]  = g1[i];
        ((float*)(smem + OFF_BE1))[i] = be1[i];
    }
    for (int i = tid; i < 480; i += NT) ((float*)(smem + OFF_DW))[i] = dw[i];
    if (tid < 3) ((float*)(smem + OFF_DB))[tid] = db[tid];
    __syncthreads();

    // fragment bases (unswizzled; swizzle applied per use with kc folded in)
    const uint32_t aun = (uint32_t)((warpRow + (l & 15)) * 128 + (l >> 4) * 16);
    const uint32_t bun = (uint32_t)(inPair * 8192 + (l & 7) * 128
                                    + ((l >> 3) & 1) * 16 + (l >> 4) * 1024);
    // exchange: [pair][inPair][lane][16] f32
    float* exTx = (float*)(smem + OFF_EXCH) + pair * 1024 + inPair * 512 + l * 16;
    const float* exRx = (const float*)(smem + OFF_EXCH) + pair * 1024
                        + (inPair ^ 1) * 512 + l * 16;
    const int barid = pair + 1;
    const int sendc = inPair ? 0 : 2;     // A sends rows+8 half, B sends rows half
    const int myrow = warpRow + (l >> 2) + (inPair ? 8 : 0);
    const uint32_t biasoff = (uint32_t)(inPair * 64 + (l & 3) * 2) * 4;

    float cst[8];

    // ============ the two layers share this macro-shaped loop ============
#pragma unroll 1
    for (int layer = 0; layer < 2; layer++) {
        const uint32_t WIoff = layer ? OFF_WI1 : OFF_WI0;
        const uint32_t WHoff = layer ? OFF_WH1 : OFF_WH0;
        const uint32_t Boff  = layer ? OFF_BIAS1 : OFF_BIAS0;
#pragma unroll
        for (int i = 0; i < 8; i++) cst[i] = 0.f;

#pragma unroll 1
        for (int t = 0; t < TT; t++) {
            float acc[8][4];
#pragma unroll
            for (int nt = 0; nt < 8; nt++) {
                float2 bq = *(const float2*)(smem + Boff + biasoff + nt * 32);
                acc[nt][0] = bq.x; acc[nt][1] = bq.y;
                acc[nt][2] = bq.x; acc[nt][3] = bq.y;
            }
            if (layer == 0)
                gemm_phase<4>(sb + OFF_X + t * TILE_B, sb + WIoff, aun, bun, acc);
            else
                gemm_phase<2>(sb + OFF_X + t * TILE_B, sb + WIoff, aun, bun, acc);
            gemm_phase<2>(sb + OFF_H, sb + WHoff, aun, bun, acc);

            // exchange the "other rows" half of the gates with the pair warp
#pragma unroll
            for (int nt = 0; nt < 8; nt++) {
                exTx[nt * 2]     = acc[nt][sendc];
                exTx[nt * 2 + 1] = acc[nt][sendc + 1];
            }
            BARP(barid);

            // cell math for my 8 cells (row = myrow, units per nt/c)
#pragma unroll
            for (int nt = 0; nt < 4; nt++) {
                float h2v[2];
#pragma unroll
                for (int c = 0; c < 2; c++) {
                    float gi, gf, gg, go;
                    if (inPair) {
                        gi = exRx[nt * 2 + c];
                        gf = exRx[(nt + 4) * 2 + c];
                        gg = acc[nt][2 + c];
                        go = acc[nt + 4][2 + c];
                    } else {
                        gi = acc[nt][c];
                        gf = acc[nt + 4][c];
                        gg = exRx[nt * 2 + c];
                        go = exRx[(nt + 4) * 2 + c];
                    }
                    float cc = cst[nt * 2 + c];
                    cc = sigm(gf) * cc + sigm(gi) * tanh_f(gg);
                    cst[nt * 2 + c] = cc;
                    h2v[c] = sigm(go) * tanh_f(cc);
                }
                __half2 hp = __floats2half2_rn(h2v[0], h2v[1]);
                uint32_t off = SWZ((uint32_t)(myrow * 128 + (nt * 8 + (l & 3) * 2) * 2));
                *(__half2*)(smem + OFF_H + off) = hp;
                *(__half2*)(smem + OFF_X + t * TILE_B + off) = hp;
            }
            BARP(barid);   // h visible to both warps of the pair before next gemm
        }
        __syncthreads();

        // ---- LN + LeakyReLU (+ head fold); layer0 also rewrites x1 ----
        if (tid < MB) {
            int b = tid;
            float s = 0.f, sq = 0.f;
#pragma unroll
            for (int t = 0; t < TT; t++)
#pragma unroll
                for (int u2 = 0; u2 < 16; u2++) {
                    uint32_t hv = *(uint32_t*)(smem + OFF_X + t * TILE_B
                                               + SWZ((uint32_t)(b * 128 + u2 * 4)));
                    float2 v = __half22float2(*(__half2*)&hv);
                    s += v.x + v.y; sq += v.x * v.x + v.y * v.y;
                }
            float mu  = s * (1.f / 160.f);
            float var = sq * (1.f / 160.f) - mu * mu;
            float rs  = rsqrtf(var + 1e-5f);
            const uint32_t Goff  = layer ? OFF_G1 : OFF_G0;
            const uint32_t BEoff = layer ? OFF_BE1 : OFF_BE0;
            float p0 = 0.f, p1 = 0.f, p2 = 0.f;
#pragma unroll
            for (int t = 0; t < TT; t++)
#pragma unroll
                for (int u2 = 0; u2 < 16; u2++) {
                    uint32_t off = SWZ((uint32_t)(b * 128 + u2 * 4));
                    uint32_t hv = *(uint32_t*)(smem + OFF_X + t * TILE_B + off);
                    float2 v = __half22float2(*(__half2*)&hv);
                    int idx = t * 32 + u2 * 2;
                    float2 gg = *(const float2*)(smem + Goff + idx * 4);
                    float2 bb = *(const float2*)(smem + BEoff + idx * 4);
                    float y0 = lrelu((v.x - mu) * rs * gg.x + bb.x);
                    float y1 = lrelu((v.y - mu) * rs * gg.y + bb.y);
                    float2 d0 = *(const float2*)(smem + OFF_DW + idx * 4);
                    float2 d1 = *(const float2*)(smem + OFF_DW + (160 + idx) * 4);
                    float2 d2 = *(const float2*)(smem + OFF_DW + (320 + idx) * 4);
                    p0 += y0 * d0.x + y1 * d0.y;
                    p1 += y0 * d1.x + y1 * d1.y;
                    p2 += y0 * d2.x + y1 * d2.y;
                    if (layer == 0)
                        *(__half2*)(smem + OFF_X + t * TILE_B + off)
                            = __floats2half2_rn(y0, y1);
                }
            // dedicated stash region (survives layer-1's exchange traffic)
            float* ph = (float*)(smem + OFF_PH) + b * 3;
            if (layer == 0) {
                ph[0] = p0; ph[1] = p1; ph[2] = p2;
            } else {
                const float* sdb = (const float*)(smem + OFF_DB);
                long long ob = (gbase + b) * 3;
                out[ob + 0] = lrelu(ph[0] + p0 + sdb[0]);
                out[ob + 1] = lrelu(ph[1] + p1 + sdb[1]);
                out[ob + 2] = lrelu(ph[2] + p2 + sdb[2]);
            }
        }
        __syncthreads();
        if (layer == 0) {
            // re-zero H for layer 1
            for (int i = tid; i < TILE_B / 16; i += NT)
                ((uint4*)(smem + OFF_H))[i] = make_uint4(0, 0, 0, 0);
            __syncthreads();
        }
    }
}

extern "C" void kernel_launch(void* const* d_in, const int* in_sizes, int n_in,
                              void* d_out, int out_size) {
    const float* data  = (const float*)d_in[0];
    const float* w_ih0 = (const float*)d_in[1];
    const float* w_hh0 = (const float*)d_in[2];
    const float* b_ih0 = (const float*)d_in[3];
    const float* b_hh0 = (const float*)d_in[4];
    const float* g0    = (const float*)d_in[5];
    const float* be0   = (const float*)d_in[6];
    const float* w_ih1 = (const float*)d_in[7];
    const float* w_hh1 = (const float*)d_in[8];
    const float* b_ih1 = (const float*)d_in[9];
    const float* b_hh1 = (const float*)d_in[10];
    const float* g1    = (const float*)d_in[11];
    const float* be1   = (const float*)d_in[12];
    const float* dw    = (const float*)d_in[13];
    const float* db    = (const float*)d_in[14];
    float* out = (float*)d_out;

    cudaFuncSetAttribute(reslstm_mma,
                         cudaFuncAttributeMaxDynamicSharedMemorySize, SMEM_TOTAL);

    int grid = B_TOTAL / MB;   // 1024
    reslstm_mma<<<grid, NT, SMEM_TOTAL>>>(
        data, w_ih0, w_hh0, b_ih0, b_hh0, g0, be0,
        w_ih1, w_hh1, b_ih1, b_hh1, g1, be1, dw, db, out);
}